// round 1
// baseline (speedup 1.0000x reference)
#include <cuda_runtime.h>
#include <math.h>

#define IC 1024
#define OC 512
#define HH 64
#define WWW 64
#define NB 2
#define NA 16384          // anchors per image = 64*64*4
#define PRE_NMS_K 6000
#define POST_NMS_K 300

// ---------------- scratch (static device allocations, allowed) ----------------
__device__ float  g_x[NB * OC * HH * WWW];   // conv output (relu'd)  ~16.8 MB
__device__ float  g_scores[NB * NA];
__device__ float4 g_boxes[NB * NA];

// orderable key for descending-float compare
__device__ __forceinline__ unsigned ordkey(float f) {
    unsigned u = __float_as_uint(f);
    return (u & 0x80000000u) ? ~u : (u | 0x80000000u);
}
#define ORD_NEG_INF 0x007FFFFFu

// ================= Kernel 1: 3x3 conv 1024->512 + bias + relu =================
// grid (8 oc-tiles, 32 row-pairs, 2 batch), 128 threads.
// Block computes out[b, oc0..oc0+63, h0..h0+1, 0..63].
// Per-thread 8x8 (oc x w) register tile; K chunked by 8 input channels.
__global__ __launch_bounds__(128) void conv_kernel(
    const float* __restrict__ in, const float* __restrict__ Wc,
    const float* __restrict__ bc)
{
    __shared__ float sW[8 * 9 * 64];   // [ic][k9][oc]   4608 floats
    __shared__ float sIn[8 * 4 * 66];  // [ic][row][w+1] 2112 floats

    const int oc0 = blockIdx.x * 64;
    const int h0  = blockIdx.y * 2;
    const int b   = blockIdx.z;

    const int tid = threadIdx.x;
    const int tz  = tid >> 6;          // 0/1: output row within pair
    const int t   = tid & 63;
    const int to0 = (t >> 3) * 8;      // oc micro-tile base
    const int tw0 = (t & 7) * 8;       // w  micro-tile base

    float acc[8][8];
#pragma unroll
    for (int i = 0; i < 8; i++)
#pragma unroll
        for (int j = 0; j < 8; j++) acc[i][j] = 0.f;

    for (int ic0 = 0; ic0 < IC; ic0 += 8) {
        __syncthreads();
        // load weights: W[(oc0+oc)][ic0+ic][kh][kw] -> sW[(ic*9+k)*64+oc]
        for (int idx = tid; idx < 4608; idx += 128) {
            int oc = idx / 72;
            int r  = idx - oc * 72;
            int ic = r / 9;
            int k  = r - ic * 9;
            sW[(ic * 9 + k) * 64 + oc] = Wc[((oc0 + oc) * IC + ic0 + ic) * 9 + k];
        }
        // load inputs rows h0-1..h0+2, cols -1..64 (zero padded)
        for (int idx = tid; idx < 2112; idx += 128) {
            int ic  = idx / 264;
            int r   = idx - ic * 264;
            int row = r / 66;
            int wb  = r - row * 66;
            int hh  = h0 - 1 + row;
            int ww  = wb - 1;
            float v = 0.f;
            if (hh >= 0 && hh < HH && ww >= 0 && ww < WWW)
                v = in[((b * IC + ic0 + ic) * HH + hh) * WWW + ww];
            sIn[idx] = v;
        }
        __syncthreads();

#pragma unroll
        for (int ic = 0; ic < 8; ic++) {
#pragma unroll
            for (int kh = 0; kh < 3; kh++) {
                float ir[10];
                const float* ip = &sIn[(ic * 4 + tz + kh) * 66 + tw0];
#pragma unroll
                for (int j = 0; j < 10; j++) ir[j] = ip[j];
#pragma unroll
                for (int kw = 0; kw < 3; kw++) {
                    float wr[8];
                    const float* wp = &sW[(ic * 9 + kh * 3 + kw) * 64 + to0];
#pragma unroll
                    for (int i = 0; i < 8; i++) wr[i] = wp[i];
#pragma unroll
                    for (int i = 0; i < 8; i++)
#pragma unroll
                        for (int j = 0; j < 8; j++)
                            acc[i][j] = fmaf(wr[i], ir[j + kw], acc[i][j]);
                }
            }
        }
    }

    const int h = h0 + tz;
#pragma unroll
    for (int i = 0; i < 8; i++) {
        float bias = bc[oc0 + to0 + i];
        float* op = &g_x[((b * OC + oc0 + to0 + i) * HH + h) * WWW + tw0];
#pragma unroll
        for (int j = 0; j < 8; j++) {
            float v = acc[i][j] + bias;
            op[j] = v > 0.f ? v : 0.f;
        }
    }
}

// ============ Kernel 2: cls/bbox heads + softmax + decode + filter ============
// grid (64 rows, 2 batch), 64 threads (one per w).
__global__ __launch_bounds__(64) void heads_kernel(
    const float* __restrict__ meta,
    const float* __restrict__ Wcls, const float* __restrict__ bcls,
    const float* __restrict__ Wbb,  const float* __restrict__ bbb)
{
    __shared__ float sw[512 * 20];
    __shared__ float sb[20];

    const int h = blockIdx.x, b = blockIdx.y, tid = threadIdx.x;

    for (int idx = tid; idx < 512 * 20; idx += 64) {
        int c = idx / 20, o = idx - c * 20;
        sw[idx] = (o < 4) ? Wcls[o * 512 + c] : Wbb[(o - 4) * 512 + c];
    }
    if (tid < 20) sb[tid] = (tid < 4) ? bcls[tid] : bbb[tid - 4];
    __syncthreads();

    const int w = tid;
    float acc[20];
#pragma unroll
    for (int o = 0; o < 20; o++) acc[o] = 0.f;

    const float* xp = g_x + ((size_t)(b * OC) * HH + h) * WWW + w;
    for (int c = 0; c < 512; c++) {
        float xv = xp[(size_t)c * HH * WWW];
        const float4* wp = reinterpret_cast<const float4*>(&sw[c * 20]);
        float4 w0 = wp[0], w1 = wp[1], w2 = wp[2], w3 = wp[3], w4 = wp[4];
        acc[0]  = fmaf(xv, w0.x, acc[0]);  acc[1]  = fmaf(xv, w0.y, acc[1]);
        acc[2]  = fmaf(xv, w0.z, acc[2]);  acc[3]  = fmaf(xv, w0.w, acc[3]);
        acc[4]  = fmaf(xv, w1.x, acc[4]);  acc[5]  = fmaf(xv, w1.y, acc[5]);
        acc[6]  = fmaf(xv, w1.z, acc[6]);  acc[7]  = fmaf(xv, w1.w, acc[7]);
        acc[8]  = fmaf(xv, w2.x, acc[8]);  acc[9]  = fmaf(xv, w2.y, acc[9]);
        acc[10] = fmaf(xv, w2.z, acc[10]); acc[11] = fmaf(xv, w2.w, acc[11]);
        acc[12] = fmaf(xv, w3.x, acc[12]); acc[13] = fmaf(xv, w3.y, acc[13]);
        acc[14] = fmaf(xv, w3.z, acc[14]); acc[15] = fmaf(xv, w3.w, acc[15]);
        acc[16] = fmaf(xv, w4.x, acc[16]); acc[17] = fmaf(xv, w4.y, acc[17]);
        acc[18] = fmaf(xv, w4.z, acc[18]); acc[19] = fmaf(xv, w4.w, acc[19]);
    }

    float s[4];
#pragma unroll
    for (int a = 0; a < 4; a++) s[a] = acc[a] + sb[a];
    float prob[4];
#pragma unroll
    for (int a = 0; a < 4; a++) {
        int p = a ^ 2;  // softmax pairing: channel a <-> a+-2
        float m  = fmaxf(s[a], s[p]);
        float ea = expf(s[a] - m);
        float eb = expf(s[p] - m);
        prob[a]  = ea / (ea + eb);
    }

    const float im_h = meta[b * 3 + 0];
    const float im_w = meta[b * 3 + 1];
    const float scl  = meta[b * 3 + 2];
    const float minsz = 16.f * scl;

    const int base = b * NA + (h * 64 + w) * 4;
#pragma unroll
    for (int a = 0; a < 4; a++) {
        float wa = (float)(64 << a);           // square anchors 64/128/256/512
        float cx = w * 16.f + 8.f;
        float cy = h * 16.f + 8.f;
        float d0 = acc[4 + a * 4 + 0] + sb[4 + a * 4 + 0];
        float d1 = acc[4 + a * 4 + 1] + sb[4 + a * 4 + 1];
        float d2 = acc[4 + a * 4 + 2] + sb[4 + a * 4 + 2];
        float d3 = acc[4 + a * 4 + 3] + sb[4 + a * 4 + 3];
        float pcx = d0 * wa + cx, pcy = d1 * wa + cy;
        float pw  = expf(d2) * wa, ph = expf(d3) * wa;
        float x1 = pcx - 0.5f * pw, y1 = pcy - 0.5f * ph;
        float x2 = pcx + 0.5f * pw, y2 = pcy + 0.5f * ph;
        x1 = fminf(fmaxf(x1, 0.f), im_w - 1.f);
        x2 = fminf(fmaxf(x2, 0.f), im_w - 1.f);
        y1 = fminf(fmaxf(y1, 0.f), im_h - 1.f);
        y2 = fminf(fmaxf(y2, 0.f), im_h - 1.f);
        bool keep = (x2 - x1 + 1.f >= minsz) && (y2 - y1 + 1.f >= minsz);
        g_scores[base + a] = keep ? prob[a] : -INFINITY;
        g_boxes[base + a]  = make_float4(x1, y1, x2, y2);
    }
}

// ================= Kernel 3: exact top-6000 mark (per image) ==================
// Binary search the 6000th-largest orderable key; ties resolved in index order
// (matches lax.top_k). Non-candidates get score = -inf in place.
__global__ __launch_bounds__(1024) void topk_kernel()
{
    const int b   = blockIdx.x;
    const int tid = threadIdx.x;
    float* scores = g_scores + b * NA;

    unsigned key[16];
    const int i0 = tid * 16;
#pragma unroll
    for (int i = 0; i < 16; i++) key[i] = ordkey(scores[i0 + i]);

    __shared__ int wsum[32];
    __shared__ int s_total;
    const int lane = tid & 31, wid = tid >> 5;

    // ---- count(keys >= cand), deterministic reduce ----
    auto count_ge = [&](unsigned cand) -> int {
        int local = 0;
#pragma unroll
        for (int i = 0; i < 16; i++) local += (key[i] >= cand) ? 1 : 0;
        for (int off = 16; off; off >>= 1)
            local += __shfl_down_sync(0xFFFFFFFFu, local, off);
        if (lane == 0) wsum[wid] = local;
        __syncthreads();
        if (tid == 0) {
            int st = 0;
            for (int k = 0; k < 32; k++) st += wsum[k];
            s_total = st;
        }
        __syncthreads();
        int r = s_total;
        __syncthreads();
        return r;
    };

    unsigned thr = 0;
    for (int bit = 31; bit >= 0; bit--) {
        unsigned cand = thr | (1u << bit);
        if (count_ge(cand) >= PRE_NMS_K) thr = cand;
    }
    const int n_gt = count_ge(thr + 1u);   // strictly greater
    const int need = PRE_NMS_K - n_gt;     // ties to accept, lowest-index first

    int my_eq = 0;
#pragma unroll
    for (int i = 0; i < 16; i++) my_eq += (key[i] == thr) ? 1 : 0;

    // block exclusive scan of my_eq (thread order == index order)
    int v = my_eq;
    for (int off = 1; off < 32; off <<= 1) {
        int tt = __shfl_up_sync(0xFFFFFFFFu, v, off);
        if (lane >= off) v += tt;
    }
    __syncthreads();
    if (lane == 31) wsum[wid] = v;
    __syncthreads();
    if (wid == 0) {
        int sv = wsum[lane];
        for (int off = 1; off < 32; off <<= 1) {
            int tt = __shfl_up_sync(0xFFFFFFFFu, sv, off);
            if (lane >= off) sv += tt;
        }
        wsum[lane] = sv;
    }
    __syncthreads();
    int rank = v - my_eq + (wid ? wsum[wid - 1] : 0);

#pragma unroll
    for (int i = 0; i < 16; i++) {
        if (key[i] == thr) {
            if (rank >= need) scores[i0 + i] = -INFINITY;
            rank++;
        } else if (key[i] < thr) {
            scores[i0 + i] = -INFINITY;
        }
    }
}

// ===================== Kernel 4: exact greedy NMS (per image) =================
// Scores live in registers (32 per thread); boxes re-read from L2 each round.
__global__ __launch_bounds__(512) void nms_kernel(float* __restrict__ out)
{
    const int b   = blockIdx.x;
    const int tid = threadIdx.x;
    const float4* boxes = g_boxes + b * NA;

    float sc[32];
    const int i0 = tid * 32;
#pragma unroll
    for (int i = 0; i < 32; i++) sc[i] = g_scores[b * NA + i0 + i];

    __shared__ unsigned long long swm[16];
    __shared__ unsigned long long s_best;
    __shared__ float4 s_box;
    __shared__ float  s_area;
    __shared__ int    s_firstj;

    const int lane = tid & 31, wid = tid >> 5;

    for (int it = 0; it < POST_NMS_K; it++) {
        // ---- argmax (max score, lowest index on tie) ----
        unsigned long long loc = ((unsigned long long)ORD_NEG_INF << 32);
#pragma unroll
        for (int i = 0; i < 32; i++) {
            unsigned long long kk =
                ((unsigned long long)ordkey(sc[i]) << 32) |
                (unsigned)(65535 - (i0 + i));
            loc = (kk > loc) ? kk : loc;
        }
        for (int off = 16; off; off >>= 1) {
            unsigned long long o = __shfl_down_sync(0xFFFFFFFFu, loc, off);
            loc = (o > loc) ? o : loc;
        }
        if (lane == 0) swm[wid] = loc;
        __syncthreads();
        if (tid < 16) {
            unsigned long long vv = swm[tid];
            for (int off = 8; off; off >>= 1) {
                unsigned long long o = __shfl_down_sync(0x0000FFFFu, vv, off);
                vv = (o > vv) ? o : vv;
            }
            if (tid == 0) s_best = vv;
        }
        __syncthreads();

        if (tid == 0) {
            unsigned long long best = s_best;
            unsigned keypart = (unsigned)(best >> 32);
            int j;
            if (keypart == ORD_NEG_INF && it > 0) j = s_firstj;  // exhausted pool
            else j = 65535 - (int)(best & 0xFFFFFFFFull);
            if (it == 0) s_firstj = j;
            float4 bx = boxes[j];
            s_box  = bx;
            s_area = (bx.z - bx.x + 1.f) * (bx.w - bx.y + 1.f);
            float* o = out + (size_t)(b * POST_NMS_K + it) * 5;
            o[0] = (float)b; o[1] = bx.x; o[2] = bx.y; o[3] = bx.z; o[4] = bx.w;
        }
        __syncthreads();

        const float4 jb = s_box;
        const float  ja = s_area;
#pragma unroll 4
        for (int i = 0; i < 32; i++) {
            float4 bb = boxes[i0 + i];
            float xx1 = fmaxf(jb.x, bb.x);
            float yy1 = fmaxf(jb.y, bb.y);
            float xx2 = fminf(jb.z, bb.z);
            float yy2 = fminf(jb.w, bb.w);
            float iw  = fmaxf(xx2 - xx1 + 1.f, 0.f);
            float ih  = fmaxf(yy2 - yy1 + 1.f, 0.f);
            float inter = iw * ih;
            float area  = (bb.z - bb.x + 1.f) * (bb.w - bb.y + 1.f);
            float iou   = inter / (ja + area - inter);
            if (iou > 0.7f) sc[i] = -INFINITY;
        }
        // next shared write (swm) is already ordered behind the last barrier
    }
}

// ================================ launcher ====================================
extern "C" void kernel_launch(void* const* d_in, const int* in_sizes, int n_in,
                              void* d_out, int out_size)
{
    const float* feat = (const float*)d_in[0];
    const float* meta = (const float*)d_in[1];
    // d_in[2] = gt_boxes (unused by the reference output)
    const float* Wc   = (const float*)d_in[3];
    const float* bc   = (const float*)d_in[4];
    const float* Wcls = (const float*)d_in[5];
    const float* bcls = (const float*)d_in[6];
    const float* Wbb  = (const float*)d_in[7];
    const float* bbb  = (const float*)d_in[8];
    float* out = (float*)d_out;

    conv_kernel<<<dim3(8, 32, 2), 128>>>(feat, Wc, bc);
    heads_kernel<<<dim3(64, 2), 64>>>(meta, Wcls, bcls, Wbb, bbb);
    topk_kernel<<<2, 1024>>>();
    nms_kernel<<<2, 512>>>(out);
}

// round 2
// speedup vs baseline: 1.1188x; 1.1188x over previous
#include <cuda_runtime.h>
#include <math.h>

#define IC 1024
#define OC 512
#define HH 64
#define WWW 64
#define NB 2
#define NA 16384          // anchors per image = 64*64*4
#define PRE_NMS_K 6000
#define POST_NMS_K 300

// conv tiling
#define ICC 8             // input channels per chunk
#define OCT 32            // oc per block
#define HT 4              // output rows per block
#define IPITCH 68         // sIn row pitch (floats), 16B aligned
#define WNUM (ICC*9*OCT)  // 2304 weight floats per chunk
#define INUM (ICC*6*IPITCH) // 3264 input floats per chunk

// ---------------- scratch (static device allocations, allowed) ----------------
__device__ float  g_x[NB * OC * HH * WWW];   // conv output (relu'd)  ~16.8 MB
__device__ float  g_scores[NB * NA];
__device__ float4 g_boxes[NB * NA];

// orderable key for descending-float compare
__device__ __forceinline__ unsigned ordkey(float f) {
    unsigned u = __float_as_uint(f);
    return (u & 0x80000000u) ? ~u : (u | 0x80000000u);
}
#define ORD_NEG_INF 0x007FFFFFu

// ---- packed f32x2 helpers (FFMA2 on sm_103a) ----
__device__ __forceinline__ unsigned long long bc2(float f) {
    unsigned long long r; unsigned u = __float_as_uint(f);
    asm("mov.b64 %0, {%1, %1};" : "=l"(r) : "r"(u));
    return r;
}
#define FMA2(d, a, b, c) \
    asm("fma.rn.f32x2 %0, %1, %2, %3;" : "=l"(d) : "l"(a), "l"(b), "l"(c))

__device__ __forceinline__ float lo32(unsigned long long v) {
    return __uint_as_float((unsigned)v);
}
__device__ __forceinline__ float hi32(unsigned long long v) {
    return __uint_as_float((unsigned)(v >> 32));
}

// ================= Kernel 1: 3x3 conv 1024->512 + bias + relu =================
// grid (16 oc-tiles, 16 h-quads, 2 batch), 128 threads, 4 blocks/SM.
// Block computes out[b, oc0..oc0+31, h0..h0+3, 0..63].
// Thread: 8 oc (as 4 f32x2 pairs) x 8 w register tile, one h row.
// Double-buffered cp.async pipeline over 128 chunks of 8 input channels.
__global__ __launch_bounds__(128, 4) void conv_kernel(
    const float* __restrict__ in, const float* __restrict__ Wc,
    const float* __restrict__ bc)
{
    __shared__ float sW[2][WNUM];
    __shared__ float sIn[2][INUM];

    const int oc0 = blockIdx.x * OCT;
    const int h0  = blockIdx.y * HT;
    const int b   = blockIdx.z;
    const int tid = threadIdx.x;

    const int tz  = tid >> 5;              // output row within quad (0..3)
    const int to0 = ((tid >> 3) & 3) * 8;  // oc micro-tile base (0..24)
    const int tw0 = (tid & 7) * 8;         // w  micro-tile base

    const unsigned sW_u0  = (unsigned)__cvta_generic_to_shared(&sW[0][0]);
    const unsigned sW_u1  = (unsigned)__cvta_generic_to_shared(&sW[1][0]);
    const unsigned sIn_u0 = (unsigned)__cvta_generic_to_shared(&sIn[0][0]);
    const unsigned sIn_u1 = (unsigned)__cvta_generic_to_shared(&sIn[1][0]);

    unsigned long long acc2[4][8];
#pragma unroll
    for (int p = 0; p < 4; p++)
#pragma unroll
        for (int j = 0; j < 8; j++) acc2[p][j] = 0ull;

    // ---- cp.async issue of one 8-ic chunk into buffer bu ----
    auto issue_chunk = [&](int ic0, int bu) {
        const unsigned sWu  = bu ? sW_u1  : sW_u0;
        const unsigned sInu = bu ? sIn_u1 : sIn_u0;
        // weights: 2304 floats, 18 per thread
#pragma unroll
        for (int i = 0; i < 18; i++) {
            int idx  = tid + i * 128;
            int oc_l = idx / 72;
            int r    = idx - oc_l * 72;
            int ic_l = r / 9;
            int k    = r - ic_l * 9;
            const float* g = Wc + ((size_t)(oc0 + oc_l) * IC + ic0 + ic_l) * 9 + k;
            unsigned s = sWu + (unsigned)(((ic_l * 9 + k) * OCT + oc_l) * 4);
            asm volatile("cp.async.ca.shared.global [%0], [%1], 4;"
                         :: "r"(s), "l"(g));
        }
        // input: 3264 floats (6 rows x 68 cols x 8 ic), zero-padded borders
#pragma unroll
        for (int i = 0; i < 26; i++) {
            int idx = tid + i * 128;
            if (idx < INUM) {
                int ic_l = idx / 408;
                int r    = idx - ic_l * 408;
                int row  = r / IPITCH;
                int col  = r - row * IPITCH;
                int hh   = h0 - 1 + row;
                int ww   = col - 1;
                bool valid = (col < 66) && (hh >= 0) && (hh < HH) &&
                             (ww >= 0) && (ww < WWW);
                const float* g = in +
                    (((size_t)b * IC + ic0 + ic_l) * HH + (valid ? hh : 0)) * WWW +
                    (valid ? ww : 0);
                unsigned s = sInu + (unsigned)(idx * 4);
                int sz = valid ? 4 : 0;
                asm volatile("cp.async.ca.shared.global [%0], [%1], 4, %2;"
                             :: "r"(s), "l"(g), "r"(sz));
            }
        }
        asm volatile("cp.async.commit_group;");
    };

    issue_chunk(0, 0);

    for (int kc = 0; kc < IC / ICC; kc++) {
        const int cur = kc & 1;
        if (kc < IC / ICC - 1) {
            issue_chunk((kc + 1) * ICC, cur ^ 1);
            asm volatile("cp.async.wait_group 1;");
        } else {
            asm volatile("cp.async.wait_group 0;");
        }
        __syncthreads();

        const float* W_ = sW[cur];
        const float* I_ = sIn[cur];

#pragma unroll 1
        for (int ic = 0; ic < ICC; ic++) {
            const float* irow = I_ + (ic * 6 + tz) * IPITCH + tw0;
            const float* wrow = W_ + ic * 9 * OCT + to0;
#pragma unroll
            for (int kh = 0; kh < 3; kh++) {
                float4 f0 = *(const float4*)(irow + kh * IPITCH);
                float4 f1 = *(const float4*)(irow + kh * IPITCH + 4);
                float4 f2 = *(const float4*)(irow + kh * IPITCH + 8);
                unsigned long long ib[10];
                ib[0] = bc2(f0.x); ib[1] = bc2(f0.y); ib[2] = bc2(f0.z); ib[3] = bc2(f0.w);
                ib[4] = bc2(f1.x); ib[5] = bc2(f1.y); ib[6] = bc2(f1.z); ib[7] = bc2(f1.w);
                ib[8] = bc2(f2.x); ib[9] = bc2(f2.y);
#pragma unroll
                for (int kw = 0; kw < 3; kw++) {
                    const ulonglong2* wp =
                        (const ulonglong2*)(wrow + (kh * 3 + kw) * OCT);
                    ulonglong2 wa = wp[0];   // oc pairs (0,1),(2,3)
                    ulonglong2 wb = wp[1];   // oc pairs (4,5),(6,7)
#pragma unroll
                    for (int j = 0; j < 8; j++) {
                        FMA2(acc2[0][j], wa.x, ib[j + kw], acc2[0][j]);
                        FMA2(acc2[1][j], wa.y, ib[j + kw], acc2[1][j]);
                        FMA2(acc2[2][j], wb.x, ib[j + kw], acc2[2][j]);
                        FMA2(acc2[3][j], wb.y, ib[j + kw], acc2[3][j]);
                    }
                }
            }
        }
        __syncthreads();
    }

    // ---- epilogue: bias + relu + store ----
    const int h = h0 + tz;
#pragma unroll
    for (int p = 0; p < 4; p++) {
#pragma unroll
        for (int s = 0; s < 2; s++) {
            int oc = oc0 + to0 + 2 * p + s;
            float bias = bc[oc];
            float* op = &g_x[((size_t)(b * OC + oc) * HH + h) * WWW + tw0];
#pragma unroll
            for (int j = 0; j < 8; j++) {
                float v = (s == 0 ? lo32(acc2[p][j]) : hi32(acc2[p][j])) + bias;
                op[j] = v > 0.f ? v : 0.f;
            }
        }
    }
}

// ============ Kernel 2: cls/bbox heads + softmax + decode + filter ============
// grid (64 rows, 2 batch), 64 threads (one per w).
__global__ __launch_bounds__(64) void heads_kernel(
    const float* __restrict__ meta,
    const float* __restrict__ Wcls, const float* __restrict__ bcls,
    const float* __restrict__ Wbb,  const float* __restrict__ bbb)
{
    __shared__ float sw[512 * 20];
    __shared__ float sb[20];

    const int h = blockIdx.x, b = blockIdx.y, tid = threadIdx.x;

    for (int idx = tid; idx < 512 * 20; idx += 64) {
        int c = idx / 20, o = idx - c * 20;
        sw[idx] = (o < 4) ? Wcls[o * 512 + c] : Wbb[(o - 4) * 512 + c];
    }
    if (tid < 20) sb[tid] = (tid < 4) ? bcls[tid] : bbb[tid - 4];
    __syncthreads();

    const int w = tid;
    float acc[20];
#pragma unroll
    for (int o = 0; o < 20; o++) acc[o] = 0.f;

    const float* xp = g_x + ((size_t)(b * OC) * HH + h) * WWW + w;
    for (int c = 0; c < 512; c++) {
        float xv = xp[(size_t)c * HH * WWW];
        const float4* wp = reinterpret_cast<const float4*>(&sw[c * 20]);
        float4 w0 = wp[0], w1 = wp[1], w2 = wp[2], w3 = wp[3], w4 = wp[4];
        acc[0]  = fmaf(xv, w0.x, acc[0]);  acc[1]  = fmaf(xv, w0.y, acc[1]);
        acc[2]  = fmaf(xv, w0.z, acc[2]);  acc[3]  = fmaf(xv, w0.w, acc[3]);
        acc[4]  = fmaf(xv, w1.x, acc[4]);  acc[5]  = fmaf(xv, w1.y, acc[5]);
        acc[6]  = fmaf(xv, w1.z, acc[6]);  acc[7]  = fmaf(xv, w1.w, acc[7]);
        acc[8]  = fmaf(xv, w2.x, acc[8]);  acc[9]  = fmaf(xv, w2.y, acc[9]);
        acc[10] = fmaf(xv, w2.z, acc[10]); acc[11] = fmaf(xv, w2.w, acc[11]);
        acc[12] = fmaf(xv, w3.x, acc[12]); acc[13] = fmaf(xv, w3.y, acc[13]);
        acc[14] = fmaf(xv, w3.z, acc[14]); acc[15] = fmaf(xv, w3.w, acc[15]);
        acc[16] = fmaf(xv, w4.x, acc[16]); acc[17] = fmaf(xv, w4.y, acc[17]);
        acc[18] = fmaf(xv, w4.z, acc[18]); acc[19] = fmaf(xv, w4.w, acc[19]);
    }

    float s[4];
#pragma unroll
    for (int a = 0; a < 4; a++) s[a] = acc[a] + sb[a];
    float prob[4];
#pragma unroll
    for (int a = 0; a < 4; a++) {
        int p = a ^ 2;  // softmax pairing: channel a <-> a+-2
        float m  = fmaxf(s[a], s[p]);
        float ea = expf(s[a] - m);
        float eb = expf(s[p] - m);
        prob[a]  = ea / (ea + eb);
    }

    const float im_h = meta[b * 3 + 0];
    const float im_w = meta[b * 3 + 1];
    const float scl  = meta[b * 3 + 2];
    const float minsz = 16.f * scl;

    const int base = b * NA + (h * 64 + w) * 4;
#pragma unroll
    for (int a = 0; a < 4; a++) {
        float wa = (float)(64 << a);           // square anchors 64/128/256/512
        float cx = w * 16.f + 8.f;
        float cy = h * 16.f + 8.f;
        float d0 = acc[4 + a * 4 + 0] + sb[4 + a * 4 + 0];
        float d1 = acc[4 + a * 4 + 1] + sb[4 + a * 4 + 1];
        float d2 = acc[4 + a * 4 + 2] + sb[4 + a * 4 + 2];
        float d3 = acc[4 + a * 4 + 3] + sb[4 + a * 4 + 3];
        float pcx = d0 * wa + cx, pcy = d1 * wa + cy;
        float pw  = expf(d2) * wa, ph = expf(d3) * wa;
        float x1 = pcx - 0.5f * pw, y1 = pcy - 0.5f * ph;
        float x2 = pcx + 0.5f * pw, y2 = pcy + 0.5f * ph;
        x1 = fminf(fmaxf(x1, 0.f), im_w - 1.f);
        x2 = fminf(fmaxf(x2, 0.f), im_w - 1.f);
        y1 = fminf(fmaxf(y1, 0.f), im_h - 1.f);
        y2 = fminf(fmaxf(y2, 0.f), im_h - 1.f);
        bool keep = (x2 - x1 + 1.f >= minsz) && (y2 - y1 + 1.f >= minsz);
        g_scores[base + a] = keep ? prob[a] : -INFINITY;
        g_boxes[base + a]  = make_float4(x1, y1, x2, y2);
    }
}

// ================= Kernel 3: exact top-6000 mark (per image) ==================
// Binary search the 6000th-largest orderable key; ties resolved in index order
// (matches lax.top_k). Non-candidates get score = -inf in place.
__global__ __launch_bounds__(1024) void topk_kernel()
{
    const int b   = blockIdx.x;
    const int tid = threadIdx.x;
    float* scores = g_scores + b * NA;

    unsigned key[16];
    const int i0 = tid * 16;
#pragma unroll
    for (int i = 0; i < 16; i++) key[i] = ordkey(scores[i0 + i]);

    __shared__ int wsum[32];
    __shared__ int s_total;
    const int lane = tid & 31, wid = tid >> 5;

    // ---- count(keys >= cand), deterministic reduce ----
    auto count_ge = [&](unsigned cand) -> int {
        int local = 0;
#pragma unroll
        for (int i = 0; i < 16; i++) local += (key[i] >= cand) ? 1 : 0;
        for (int off = 16; off; off >>= 1)
            local += __shfl_down_sync(0xFFFFFFFFu, local, off);
        if (lane == 0) wsum[wid] = local;
        __syncthreads();
        if (tid == 0) {
            int st = 0;
            for (int k = 0; k < 32; k++) st += wsum[k];
            s_total = st;
        }
        __syncthreads();
        int r = s_total;
        __syncthreads();
        return r;
    };

    unsigned thr = 0;
    for (int bit = 31; bit >= 0; bit--) {
        unsigned cand = thr | (1u << bit);
        if (count_ge(cand) >= PRE_NMS_K) thr = cand;
    }
    const int n_gt = count_ge(thr + 1u);   // strictly greater
    const int need = PRE_NMS_K - n_gt;     // ties to accept, lowest-index first

    int my_eq = 0;
#pragma unroll
    for (int i = 0; i < 16; i++) my_eq += (key[i] == thr) ? 1 : 0;

    // block exclusive scan of my_eq (thread order == index order)
    int v = my_eq;
    for (int off = 1; off < 32; off <<= 1) {
        int tt = __shfl_up_sync(0xFFFFFFFFu, v, off);
        if (lane >= off) v += tt;
    }
    __syncthreads();
    if (lane == 31) wsum[wid] = v;
    __syncthreads();
    if (wid == 0) {
        int sv = wsum[lane];
        for (int off = 1; off < 32; off <<= 1) {
            int tt = __shfl_up_sync(0xFFFFFFFFu, sv, off);
            if (lane >= off) sv += tt;
        }
        wsum[lane] = sv;
    }
    __syncthreads();
    int rank = v - my_eq + (wid ? wsum[wid - 1] : 0);

#pragma unroll
    for (int i = 0; i < 16; i++) {
        if (key[i] == thr) {
            if (rank >= need) scores[i0 + i] = -INFINITY;
            rank++;
        } else if (key[i] < thr) {
            scores[i0 + i] = -INFINITY;
        }
    }
}

// ===================== Kernel 4: exact greedy NMS (per image) =================
// Scores live in registers (32 per thread); boxes re-read from L2 each round.
__global__ __launch_bounds__(512) void nms_kernel(float* __restrict__ out)
{
    const int b   = blockIdx.x;
    const int tid = threadIdx.x;
    const float4* boxes = g_boxes + b * NA;

    float sc[32];
    const int i0 = tid * 32;
#pragma unroll
    for (int i = 0; i < 32; i++) sc[i] = g_scores[b * NA + i0 + i];

    __shared__ unsigned long long swm[16];
    __shared__ unsigned long long s_best;
    __shared__ float4 s_box;
    __shared__ float  s_area;
    __shared__ int    s_firstj;

    const int lane = tid & 31, wid = tid >> 5;

    for (int it = 0; it < POST_NMS_K; it++) {
        // ---- argmax (max score, lowest index on tie) ----
        unsigned long long loc = ((unsigned long long)ORD_NEG_INF << 32);
#pragma unroll
        for (int i = 0; i < 32; i++) {
            unsigned long long kk =
                ((unsigned long long)ordkey(sc[i]) << 32) |
                (unsigned)(65535 - (i0 + i));
            loc = (kk > loc) ? kk : loc;
        }
        for (int off = 16; off; off >>= 1) {
            unsigned long long o = __shfl_down_sync(0xFFFFFFFFu, loc, off);
            loc = (o > loc) ? o : loc;
        }
        if (lane == 0) swm[wid] = loc;
        __syncthreads();
        if (tid < 16) {
            unsigned long long vv = swm[tid];
            for (int off = 8; off; off >>= 1) {
                unsigned long long o = __shfl_down_sync(0x0000FFFFu, vv, off);
                vv = (o > vv) ? o : vv;
            }
            if (tid == 0) s_best = vv;
        }
        __syncthreads();

        if (tid == 0) {
            unsigned long long best = s_best;
            unsigned keypart = (unsigned)(best >> 32);
            int j;
            if (keypart == ORD_NEG_INF && it > 0) j = s_firstj;  // exhausted pool
            else j = 65535 - (int)(best & 0xFFFFFFFFull);
            if (it == 0) s_firstj = j;
            float4 bx = boxes[j];
            s_box  = bx;
            s_area = (bx.z - bx.x + 1.f) * (bx.w - bx.y + 1.f);
            float* o = out + (size_t)(b * POST_NMS_K + it) * 5;
            o[0] = (float)b; o[1] = bx.x; o[2] = bx.y; o[3] = bx.z; o[4] = bx.w;
        }
        __syncthreads();

        const float4 jb = s_box;
        const float  ja = s_area;
#pragma unroll 4
        for (int i = 0; i < 32; i++) {
            float4 bb = boxes[i0 + i];
            float xx1 = fmaxf(jb.x, bb.x);
            float yy1 = fmaxf(jb.y, bb.y);
            float xx2 = fminf(jb.z, bb.z);
            float yy2 = fminf(jb.w, bb.w);
            float iw  = fmaxf(xx2 - xx1 + 1.f, 0.f);
            float ih  = fmaxf(yy2 - yy1 + 1.f, 0.f);
            float inter = iw * ih;
            float area  = (bb.z - bb.x + 1.f) * (bb.w - bb.y + 1.f);
            float iou   = inter / (ja + area - inter);
            if (iou > 0.7f) sc[i] = -INFINITY;
        }
        // next shared write (swm) is already ordered behind the last barrier
    }
}

// ================================ launcher ====================================
extern "C" void kernel_launch(void* const* d_in, const int* in_sizes, int n_in,
                              void* d_out, int out_size)
{
    const float* feat = (const float*)d_in[0];
    const float* meta = (const float*)d_in[1];
    // d_in[2] = gt_boxes (unused by the reference output)
    const float* Wc   = (const float*)d_in[3];
    const float* bc   = (const float*)d_in[4];
    const float* Wcls = (const float*)d_in[5];
    const float* bcls = (const float*)d_in[6];
    const float* Wbb  = (const float*)d_in[7];
    const float* bbb  = (const float*)d_in[8];
    float* out = (float*)d_out;

    conv_kernel<<<dim3(16, 16, 2), 128>>>(feat, Wc, bc);
    heads_kernel<<<dim3(64, 2), 64>>>(meta, Wcls, bcls, Wbb, bbb);
    topk_kernel<<<2, 1024>>>();
    nms_kernel<<<2, 512>>>(out);
}

// round 3
// speedup vs baseline: 1.2750x; 1.1396x over previous
#include <cuda_runtime.h>
#include <math.h>

#define IC 1024
#define OC 512
#define HH 64
#define WWW 64
#define NB 2
#define NA 16384          // anchors per image = 64*64*4
#define PRE_NMS_K 6000
#define POST_NMS_K 300

// conv tiling
#define ICC 8             // input channels per chunk
#define OCT 32            // oc per block
#define HT 4              // output rows per block
#define IPITCH 68         // padded input row pitch (floats), 16B aligned
#define WNUM (ICC*9*OCT)          // 2304 weight floats per chunk
#define INUM (ICC*6*IPITCH)       // 3264 input floats per chunk (6 rows x 68)
#define NCHUNK (IC/ICC)           // 128
#define NOCT (OC/OCT)             // 16

// ---------------- scratch (static device allocations, allowed) ----------------
__device__ float  g_x[NB * OC * HH * WWW];     // conv output (relu'd) ~16.8 MB
__device__ float  g_wr[NCHUNK * NOCT * WNUM];  // reordered weights   ~18.9 MB
__device__ float  g_ipad[NB * IC * 66 * IPITCH]; // padded input      ~36.8 MB
__device__ float  g_scores[NB * NA];
__device__ float4 g_boxes[NB * NA];

// orderable key for descending-float compare
__device__ __forceinline__ unsigned ordkey(float f) {
    unsigned u = __float_as_uint(f);
    return (u & 0x80000000u) ? ~u : (u | 0x80000000u);
}
#define ORD_NEG_INF 0x007FFFFFu

// ---- packed f32x2 helpers (FFMA2 on sm_103a) ----
__device__ __forceinline__ unsigned long long bc2(float f) {
    unsigned long long r; unsigned u = __float_as_uint(f);
    asm("mov.b64 %0, {%1, %1};" : "=l"(r) : "r"(u));
    return r;
}
#define FMA2(d, a, b, c) \
    asm("fma.rn.f32x2 %0, %1, %2, %3;" : "=l"(d) : "l"(a), "l"(b), "l"(c))

__device__ __forceinline__ float lo32(unsigned long long v) {
    return __uint_as_float((unsigned)v);
}
__device__ __forceinline__ float hi32(unsigned long long v) {
    return __uint_as_float((unsigned)(v >> 32));
}

// ============ Pre-pass A: reorder weights into smem chunk layout ==============
// g_wr[(kc*16 + ot)*2304 + (ic_l*9 + k)*32 + oc_l] =
//     Wc[((ot*32 + oc_l)*1024 + kc*8 + ic_l)*9 + k]
__global__ __launch_bounds__(256) void prep_weights(const float* __restrict__ Wc)
{
    int idx = blockIdx.x * 256 + threadIdx.x;
    if (idx >= NCHUNK * NOCT * WNUM) return;
    int c  = idx / (NOCT * WNUM);
    int r  = idx - c * (NOCT * WNUM);
    int ot = r / WNUM;
    int e  = r - ot * WNUM;
    int icl = e / 288;             // 9*32
    int e2  = e - icl * 288;
    int k   = e2 >> 5;
    int ocl = e2 & 31;
    g_wr[idx] = Wc[((size_t)(ot * 32 + ocl) * IC + c * ICC + icl) * 9 + k];
}

// ============ Pre-pass B: zero-pad input into [b][ic][66][68] =================
__global__ __launch_bounds__(256) void prep_input(const float* __restrict__ in)
{
    int idx = blockIdx.x * 256 + threadIdx.x;
    const int TOT = NB * IC * 66 * IPITCH;
    if (idx >= TOT) return;
    int bi  = idx / (66 * IPITCH);     // b*IC + ic
    int r   = idx - bi * (66 * IPITCH);
    int row = r / IPITCH;
    int col = r - row * IPITCH;
    int h   = row - 1;
    int w   = col - 1;
    float v = 0.f;
    if (h >= 0 && h < HH && w >= 0 && w < WWW && col < 66)
        v = in[((size_t)bi * HH + h) * WWW + w];
    g_ipad[idx] = v;
}

// ================= Kernel 1: 3x3 conv 1024->512 + bias + relu =================
// grid (16 oc-tiles, 16 h-quads, 2 batch), 128 threads, 3 blocks/SM.
// Block computes out[b, oc0..oc0+31, h0..h0+3, 0..63].
// Thread: 8 oc (4 f32x2 pairs) x 8 w register tile, one h row.
// Double-buffered cp.async (contiguous 16B copies, no masks/div in steady state)
__global__ __launch_bounds__(128, 3) void conv_kernel(const float* __restrict__ bc)
{
    __shared__ float sW[2][WNUM];
    __shared__ float sIn[2][INUM];

    const int oc0 = blockIdx.x * OCT;
    const int h0  = blockIdx.y * HT;
    const int b   = blockIdx.z;
    const int tid = threadIdx.x;

    const int tz  = tid >> 5;              // output row within quad (0..3)
    const int to0 = ((tid >> 3) & 3) * 8;  // oc micro-tile base (0..24)
    const int tw0 = (tid & 7) * 8;         // w  micro-tile base

    const unsigned sW_u[2] = {
        (unsigned)__cvta_generic_to_shared(&sW[0][0]),
        (unsigned)__cvta_generic_to_shared(&sW[1][0]) };
    const unsigned sIn_u[2] = {
        (unsigned)__cvta_generic_to_shared(&sIn[0][0]),
        (unsigned)__cvta_generic_to_shared(&sIn[1][0]) };

    // ---- per-thread source base addresses (chunk-invariant decomposition) ----
    // weights: 576 float4 per chunk; slots idx4 = tid + s*128, s=0..4 (last masked)
    const float* wbase = g_wr + (size_t)blockIdx.x * WNUM;   // + kc*NOCT*WNUM per chunk
    // input: 816 float4 per chunk; idx4 -> (ic_l, row, c4)
    //   src = g_ipad[((b*IC + ic0 + ic_l)*66 + h0 + row)*68 + c4*4]
    int i_icl[7], i_off[7];  // per-slot: ic_l and float-offset within (ic)-plane set
#pragma unroll
    for (int s = 0; s < 7; s++) {
        int idx4 = tid + s * 128;
        int icl  = idx4 / 102;             // 102 float4 per ic (6 rows x 17)
        int r    = idx4 - icl * 102;
        int row  = r / 17;
        int c4   = r - row * 17;
        i_icl[s] = icl;
        i_off[s] = (h0 + row) * IPITCH + c4 * 4;
    }

    unsigned long long acc2[4][8];
#pragma unroll
    for (int p = 0; p < 4; p++)
#pragma unroll
        for (int j = 0; j < 8; j++) acc2[p][j] = 0ull;

    auto issue_chunk = [&](int kc, int bu) {
        const unsigned sWu  = sW_u[bu];
        const unsigned sInu = sIn_u[bu];
        const float* ws = wbase + (size_t)kc * (NOCT * WNUM);
#pragma unroll
        for (int s = 0; s < 5; s++) {
            int idx4 = tid + s * 128;
            if (idx4 < WNUM / 4) {
                const float* g = ws + idx4 * 4;
                asm volatile("cp.async.cg.shared.global [%0], [%1], 16;"
                             :: "r"(sWu + (unsigned)(idx4 * 16)), "l"(g));
            }
        }
        const int ic0 = kc * ICC;
#pragma unroll
        for (int s = 0; s < 7; s++) {
            int idx4 = tid + s * 128;
            if (idx4 < INUM / 4) {
                const float* g = g_ipad +
                    ((size_t)(b * IC + ic0 + i_icl[s]) * 66) * IPITCH + i_off[s];
                asm volatile("cp.async.cg.shared.global [%0], [%1], 16;"
                             :: "r"(sInu + (unsigned)(idx4 * 16)), "l"(g));
            }
        }
        asm volatile("cp.async.commit_group;");
    };

    issue_chunk(0, 0);

    for (int kc = 0; kc < NCHUNK; kc++) {
        const int cur = kc & 1;
        if (kc < NCHUNK - 1) {
            issue_chunk(kc + 1, cur ^ 1);
            asm volatile("cp.async.wait_group 1;");
        } else {
            asm volatile("cp.async.wait_group 0;");
        }
        __syncthreads();

        const float* W_ = sW[cur];
        const float* I_ = sIn[cur];

#pragma unroll 1
        for (int ic = 0; ic < ICC; ic++) {
            const float* irow = I_ + (ic * 6 + tz) * IPITCH + tw0;
            const float* wrow = W_ + ic * 9 * OCT + to0;
#pragma unroll
            for (int kh = 0; kh < 3; kh++) {
                float4 f0 = *(const float4*)(irow + kh * IPITCH);
                float4 f1 = *(const float4*)(irow + kh * IPITCH + 4);
                float4 f2 = *(const float4*)(irow + kh * IPITCH + 8);
                unsigned long long ib[10];
                ib[0] = bc2(f0.x); ib[1] = bc2(f0.y); ib[2] = bc2(f0.z); ib[3] = bc2(f0.w);
                ib[4] = bc2(f1.x); ib[5] = bc2(f1.y); ib[6] = bc2(f1.z); ib[7] = bc2(f1.w);
                ib[8] = bc2(f2.x); ib[9] = bc2(f2.y);
#pragma unroll
                for (int kw = 0; kw < 3; kw++) {
                    const ulonglong2* wp =
                        (const ulonglong2*)(wrow + (kh * 3 + kw) * OCT);
                    ulonglong2 wa = wp[0];   // oc pairs (0,1),(2,3)
                    ulonglong2 wb = wp[1];   // oc pairs (4,5),(6,7)
#pragma unroll
                    for (int j = 0; j < 8; j++) {
                        FMA2(acc2[0][j], wa.x, ib[j + kw], acc2[0][j]);
                        FMA2(acc2[1][j], wa.y, ib[j + kw], acc2[1][j]);
                        FMA2(acc2[2][j], wb.x, ib[j + kw], acc2[2][j]);
                        FMA2(acc2[3][j], wb.y, ib[j + kw], acc2[3][j]);
                    }
                }
            }
        }
        __syncthreads();
    }

    // ---- epilogue: bias + relu + store ----
    const int h = h0 + tz;
#pragma unroll
    for (int p = 0; p < 4; p++) {
#pragma unroll
        for (int s = 0; s < 2; s++) {
            int oc = oc0 + to0 + 2 * p + s;
            float bias = bc[oc];
            float* op = &g_x[((size_t)(b * OC + oc) * HH + h) * WWW + tw0];
#pragma unroll
            for (int j = 0; j < 8; j++) {
                float v = (s == 0 ? lo32(acc2[p][j]) : hi32(acc2[p][j])) + bias;
                op[j] = v > 0.f ? v : 0.f;
            }
        }
    }
}

// ============ Kernel 2: cls/bbox heads + softmax + decode + filter ============
// grid (64 rows, 2 batch), 64 threads (one per w).
__global__ __launch_bounds__(64) void heads_kernel(
    const float* __restrict__ meta,
    const float* __restrict__ Wcls, const float* __restrict__ bcls,
    const float* __restrict__ Wbb,  const float* __restrict__ bbb)
{
    __shared__ float sw[512 * 20];
    __shared__ float sb[20];

    const int h = blockIdx.x, b = blockIdx.y, tid = threadIdx.x;

    for (int idx = tid; idx < 512 * 20; idx += 64) {
        int c = idx / 20, o = idx - c * 20;
        sw[idx] = (o < 4) ? Wcls[o * 512 + c] : Wbb[(o - 4) * 512 + c];
    }
    if (tid < 20) sb[tid] = (tid < 4) ? bcls[tid] : bbb[tid - 4];
    __syncthreads();

    const int w = tid;
    float acc[20];
#pragma unroll
    for (int o = 0; o < 20; o++) acc[o] = 0.f;

    const float* xp = g_x + ((size_t)(b * OC) * HH + h) * WWW + w;
    for (int c = 0; c < 512; c++) {
        float xv = xp[(size_t)c * HH * WWW];
        const float4* wp = reinterpret_cast<const float4*>(&sw[c * 20]);
        float4 w0 = wp[0], w1 = wp[1], w2 = wp[2], w3 = wp[3], w4 = wp[4];
        acc[0]  = fmaf(xv, w0.x, acc[0]);  acc[1]  = fmaf(xv, w0.y, acc[1]);
        acc[2]  = fmaf(xv, w0.z, acc[2]);  acc[3]  = fmaf(xv, w0.w, acc[3]);
        acc[4]  = fmaf(xv, w1.x, acc[4]);  acc[5]  = fmaf(xv, w1.y, acc[5]);
        acc[6]  = fmaf(xv, w1.z, acc[6]);  acc[7]  = fmaf(xv, w1.w, acc[7]);
        acc[8]  = fmaf(xv, w2.x, acc[8]);  acc[9]  = fmaf(xv, w2.y, acc[9]);
        acc[10] = fmaf(xv, w2.z, acc[10]); acc[11] = fmaf(xv, w2.w, acc[11]);
        acc[12] = fmaf(xv, w3.x, acc[12]); acc[13] = fmaf(xv, w3.y, acc[13]);
        acc[14] = fmaf(xv, w3.z, acc[14]); acc[15] = fmaf(xv, w3.w, acc[15]);
        acc[16] = fmaf(xv, w4.x, acc[16]); acc[17] = fmaf(xv, w4.y, acc[17]);
        acc[18] = fmaf(xv, w4.z, acc[18]); acc[19] = fmaf(xv, w4.w, acc[19]);
    }

    float s[4];
#pragma unroll
    for (int a = 0; a < 4; a++) s[a] = acc[a] + sb[a];
    float prob[4];
#pragma unroll
    for (int a = 0; a < 4; a++) {
        int p = a ^ 2;  // softmax pairing: channel a <-> a+-2
        float m  = fmaxf(s[a], s[p]);
        float ea = expf(s[a] - m);
        float eb = expf(s[p] - m);
        prob[a]  = ea / (ea + eb);
    }

    const float im_h = meta[b * 3 + 0];
    const float im_w = meta[b * 3 + 1];
    const float scl  = meta[b * 3 + 2];
    const float minsz = 16.f * scl;

    const int base = b * NA + (h * 64 + w) * 4;
#pragma unroll
    for (int a = 0; a < 4; a++) {
        float wa = (float)(64 << a);           // square anchors 64/128/256/512
        float cx = w * 16.f + 8.f;
        float cy = h * 16.f + 8.f;
        float d0 = acc[4 + a * 4 + 0] + sb[4 + a * 4 + 0];
        float d1 = acc[4 + a * 4 + 1] + sb[4 + a * 4 + 1];
        float d2 = acc[4 + a * 4 + 2] + sb[4 + a * 4 + 2];
        float d3 = acc[4 + a * 4 + 3] + sb[4 + a * 4 + 3];
        float pcx = d0 * wa + cx, pcy = d1 * wa + cy;
        float pw  = expf(d2) * wa, ph = expf(d3) * wa;
        float x1 = pcx - 0.5f * pw, y1 = pcy - 0.5f * ph;
        float x2 = pcx + 0.5f * pw, y2 = pcy + 0.5f * ph;
        x1 = fminf(fmaxf(x1, 0.f), im_w - 1.f);
        x2 = fminf(fmaxf(x2, 0.f), im_w - 1.f);
        y1 = fminf(fmaxf(y1, 0.f), im_h - 1.f);
        y2 = fminf(fmaxf(y2, 0.f), im_h - 1.f);
        bool keep = (x2 - x1 + 1.f >= minsz) && (y2 - y1 + 1.f >= minsz);
        g_scores[base + a] = keep ? prob[a] : -INFINITY;
        g_boxes[base + a]  = make_float4(x1, y1, x2, y2);
    }
}

// ================= Kernel 3: exact top-6000 mark (per image) ==================
__global__ __launch_bounds__(1024) void topk_kernel()
{
    const int b   = blockIdx.x;
    const int tid = threadIdx.x;
    float* scores = g_scores + b * NA;

    unsigned key[16];
    const int i0 = tid * 16;
#pragma unroll
    for (int i = 0; i < 16; i++) key[i] = ordkey(scores[i0 + i]);

    __shared__ int wsum[32];
    __shared__ int s_total;
    const int lane = tid & 31, wid = tid >> 5;

    auto count_ge = [&](unsigned cand) -> int {
        int local = 0;
#pragma unroll
        for (int i = 0; i < 16; i++) local += (key[i] >= cand) ? 1 : 0;
        for (int off = 16; off; off >>= 1)
            local += __shfl_down_sync(0xFFFFFFFFu, local, off);
        if (lane == 0) wsum[wid] = local;
        __syncthreads();
        if (tid == 0) {
            int st = 0;
            for (int k = 0; k < 32; k++) st += wsum[k];
            s_total = st;
        }
        __syncthreads();
        int r = s_total;
        __syncthreads();
        return r;
    };

    unsigned thr = 0;
    for (int bit = 31; bit >= 0; bit--) {
        unsigned cand = thr | (1u << bit);
        if (count_ge(cand) >= PRE_NMS_K) thr = cand;
    }
    const int n_gt = count_ge(thr + 1u);   // strictly greater
    const int need = PRE_NMS_K - n_gt;     // ties to accept, lowest-index first

    int my_eq = 0;
#pragma unroll
    for (int i = 0; i < 16; i++) my_eq += (key[i] == thr) ? 1 : 0;

    int v = my_eq;
    for (int off = 1; off < 32; off <<= 1) {
        int tt = __shfl_up_sync(0xFFFFFFFFu, v, off);
        if (lane >= off) v += tt;
    }
    __syncthreads();
    if (lane == 31) wsum[wid] = v;
    __syncthreads();
    if (wid == 0) {
        int sv = wsum[lane];
        for (int off = 1; off < 32; off <<= 1) {
            int tt = __shfl_up_sync(0xFFFFFFFFu, sv, off);
            if (lane >= off) sv += tt;
        }
        wsum[lane] = sv;
    }
    __syncthreads();
    int rank = v - my_eq + (wid ? wsum[wid - 1] : 0);

#pragma unroll
    for (int i = 0; i < 16; i++) {
        if (key[i] == thr) {
            if (rank >= need) scores[i0 + i] = -INFINITY;
            rank++;
        } else if (key[i] < thr) {
            scores[i0 + i] = -INFINITY;
        }
    }
}

// ===================== Kernel 4: exact greedy NMS (per image) =================
__global__ __launch_bounds__(512) void nms_kernel(float* __restrict__ out)
{
    const int b   = blockIdx.x;
    const int tid = threadIdx.x;
    const float4* boxes = g_boxes + b * NA;

    float sc[32];
    const int i0 = tid * 32;
#pragma unroll
    for (int i = 0; i < 32; i++) sc[i] = g_scores[b * NA + i0 + i];

    __shared__ unsigned long long swm[16];
    __shared__ unsigned long long s_best;
    __shared__ float4 s_box;
    __shared__ float  s_area;
    __shared__ int    s_firstj;

    const int lane = tid & 31, wid = tid >> 5;

    for (int it = 0; it < POST_NMS_K; it++) {
        unsigned long long loc = ((unsigned long long)ORD_NEG_INF << 32);
#pragma unroll
        for (int i = 0; i < 32; i++) {
            unsigned long long kk =
                ((unsigned long long)ordkey(sc[i]) << 32) |
                (unsigned)(65535 - (i0 + i));
            loc = (kk > loc) ? kk : loc;
        }
        for (int off = 16; off; off >>= 1) {
            unsigned long long o = __shfl_down_sync(0xFFFFFFFFu, loc, off);
            loc = (o > loc) ? o : loc;
        }
        if (lane == 0) swm[wid] = loc;
        __syncthreads();
        if (tid < 16) {
            unsigned long long vv = swm[tid];
            for (int off = 8; off; off >>= 1) {
                unsigned long long o = __shfl_down_sync(0x0000FFFFu, vv, off);
                vv = (o > vv) ? o : vv;
            }
            if (tid == 0) s_best = vv;
        }
        __syncthreads();

        if (tid == 0) {
            unsigned long long best = s_best;
            unsigned keypart = (unsigned)(best >> 32);
            int j;
            if (keypart == ORD_NEG_INF && it > 0) j = s_firstj;  // exhausted pool
            else j = 65535 - (int)(best & 0xFFFFFFFFull);
            if (it == 0) s_firstj = j;
            float4 bx = boxes[j];
            s_box  = bx;
            s_area = (bx.z - bx.x + 1.f) * (bx.w - bx.y + 1.f);
            float* o = out + (size_t)(b * POST_NMS_K + it) * 5;
            o[0] = (float)b; o[1] = bx.x; o[2] = bx.y; o[3] = bx.z; o[4] = bx.w;
        }
        __syncthreads();

        const float4 jb = s_box;
        const float  ja = s_area;
#pragma unroll 4
        for (int i = 0; i < 32; i++) {
            float4 bb = boxes[i0 + i];
            float xx1 = fmaxf(jb.x, bb.x);
            float yy1 = fmaxf(jb.y, bb.y);
            float xx2 = fminf(jb.z, bb.z);
            float yy2 = fminf(jb.w, bb.w);
            float iw  = fmaxf(xx2 - xx1 + 1.f, 0.f);
            float ih  = fmaxf(yy2 - yy1 + 1.f, 0.f);
            float inter = iw * ih;
            float area  = (bb.z - bb.x + 1.f) * (bb.w - bb.y + 1.f);
            float iou   = inter / (ja + area - inter);
            if (iou > 0.7f) sc[i] = -INFINITY;
        }
    }
}

// ================================ launcher ====================================
extern "C" void kernel_launch(void* const* d_in, const int* in_sizes, int n_in,
                              void* d_out, int out_size)
{
    const float* feat = (const float*)d_in[0];
    const float* meta = (const float*)d_in[1];
    // d_in[2] = gt_boxes (unused by the reference output)
    const float* Wc   = (const float*)d_in[3];
    const float* bc   = (const float*)d_in[4];
    const float* Wcls = (const float*)d_in[5];
    const float* bcls = (const float*)d_in[6];
    const float* Wbb  = (const float*)d_in[7];
    const float* bbb  = (const float*)d_in[8];
    float* out = (float*)d_out;

    prep_weights<<<(NCHUNK * NOCT * WNUM + 255) / 256, 256>>>(Wc);
    prep_input<<<(NB * IC * 66 * IPITCH + 255) / 256, 256>>>(feat);
    conv_kernel<<<dim3(16, 16, 2), 128>>>(bc);
    heads_kernel<<<dim3(64, 2), 64>>>(meta, Wcls, bcls, Wbb, bbb);
    topk_kernel<<<2, 1024>>>();
    nms_kernel<<<2, 512>>>(out);
}